// round 2
// baseline (speedup 1.0000x reference)
#include <cuda_runtime.h>
#include <math.h>

#define N_NODES 100000
#define D 128
#define BN_EPS 1e-5f

// Scratch (allocation-free: __device__ globals)
__device__ float g_h[(size_t)N_NODES * D];     // GEMM output (messages source)
__device__ float g_agg[(size_t)N_NODES * D];   // scatter-add accumulator
__device__ float g_stats[2 * D];               // per-column sum, sumsq
__device__ float g_ab[2 * D];                  // BN affine: a=gamma*inv_std, b=beta-mu*a

// ---------------- zero kernels ----------------
__global__ void zero_agg_kernel() {
    size_t total = (size_t)N_NODES * D / 4;
    float4 z = make_float4(0.f, 0.f, 0.f, 0.f);
    float4* p = reinterpret_cast<float4*>(g_agg);
    for (size_t i = blockIdx.x * (size_t)blockDim.x + threadIdx.x; i < total;
         i += (size_t)gridDim.x * blockDim.x)
        p[i] = z;
}

__global__ void zero_stats_kernel() {
    int t = threadIdx.x;
    if (t < 2 * D) g_stats[t] = 0.f;
}

// ---------------- GEMM: H = f(X) @ W ----------------
// f(x) = x (layer 0) or relu(a*x + b) (BN+ReLU fused into the load).
// Block: 128 threads (one per output column), 32 rows per block.
__global__ __launch_bounds__(128) void gemm_kernel(
    const float* __restrict__ Xin,   // null => read g_agg
    const float* __restrict__ W,     // [D, D] row-major, W[k*D + j]
    int use_bn)
{
    __shared__ float xs[32][D];
    const float* X = Xin ? Xin : g_agg;
    int col = threadIdx.x;
    size_t row0 = (size_t)blockIdx.x * 32;

    float a = 1.f, b = 0.f;
    if (use_bn) { a = g_ab[col]; b = g_ab[D + col]; }

    #pragma unroll 4
    for (int r = 0; r < 32; r++) {
        float v = X[(row0 + r) * D + col];
        if (use_bn) v = fmaxf(fmaf(v, a, b), 0.f);
        xs[r][col] = v;
    }
    __syncthreads();

    float acc[32];
    #pragma unroll
    for (int r = 0; r < 32; r++) acc[r] = 0.f;

    #pragma unroll 1
    for (int k = 0; k < D; k += 4) {
        float w0 = W[(k + 0) * D + col];
        float w1 = W[(k + 1) * D + col];
        float w2 = W[(k + 2) * D + col];
        float w3 = W[(k + 3) * D + col];
        #pragma unroll
        for (int r = 0; r < 32; r++) {
            float4 xv = *reinterpret_cast<const float4*>(&xs[r][k]);
            acc[r] = fmaf(xv.x, w0, acc[r]);
            acc[r] = fmaf(xv.y, w1, acc[r]);
            acc[r] = fmaf(xv.z, w2, acc[r]);
            acc[r] = fmaf(xv.w, w3, acc[r]);
        }
    }

    #pragma unroll 4
    for (int r = 0; r < 32; r++)
        g_h[(row0 + r) * D + col] = acc[r];
}

// ---------------- edge scatter: agg[dst] += h[src] ----------------
// One warp per edge; each lane moves one float4 (4 cols) and issues a single
// vectorized red.global.add.v4.f32 (sm_90+), quartering RED op count.
__global__ __launch_bounds__(256) void scatter_kernel(
    const int* __restrict__ src, const int* __restrict__ dst, int E)
{
    int gw = (int)((blockIdx.x * (size_t)blockDim.x + threadIdx.x) >> 5);
    int lane = threadIdx.x & 31;
    if (gw >= E) return;
    int s = __ldg(&src[gw]);
    int d = __ldg(&dst[gw]);
    float4 v = *reinterpret_cast<const float4*>(&g_h[(size_t)s * D + lane * 4]);
    float* ap = &g_agg[(size_t)d * D + lane * 4];
    asm volatile("red.global.add.v4.f32 [%0], {%1, %2, %3, %4};"
                 :: "l"(ap), "f"(v.x), "f"(v.y), "f"(v.z), "f"(v.w)
                 : "memory");
}

// ---------------- BN column stats over g_agg ----------------
// 256 threads: col = t&127, two row-subgroups; grid-stride over rows.
__global__ __launch_bounds__(256) void stats_kernel(int n)
{
    int col = threadIdx.x & (D - 1);
    int half = threadIdx.x >> 7;  // 0 or 1
    float s = 0.f, s2 = 0.f;
    for (int r = blockIdx.x * 2 + half; r < n; r += gridDim.x * 2) {
        float v = g_agg[(size_t)r * D + col];
        s += v;
        s2 = fmaf(v, v, s2);
    }
    __shared__ float sh[2 * D];
    if (half == 1) { sh[col] = s; sh[D + col] = s2; }
    __syncthreads();
    if (half == 0) {
        s += sh[col];
        s2 += sh[D + col];
        atomicAdd(&g_stats[col], s);
        atomicAdd(&g_stats[D + col], s2);
    }
}

__global__ void ab_kernel(const float* __restrict__ gamma,
                          const float* __restrict__ beta, int n)
{
    int col = threadIdx.x;
    if (col >= D) return;
    float inv_n = 1.f / (float)n;
    float mu = g_stats[col] * inv_n;
    float var = fmaf(-mu, mu, g_stats[D + col] * inv_n);
    float inv = rsqrtf(var + BN_EPS);
    float a = gamma[col] * inv;
    g_ab[col] = a;
    g_ab[D + col] = fmaf(-mu, a, beta[col]);
}

// ---------------- log_softmax over rows of g_agg -> out ----------------
__global__ __launch_bounds__(256) void lsm_kernel(float* __restrict__ out, int n)
{
    int row = (int)((blockIdx.x * (size_t)blockDim.x + threadIdx.x) >> 5);
    int lane = threadIdx.x & 31;
    if (row >= n) return;
    float4 v = *reinterpret_cast<const float4*>(&g_agg[(size_t)row * D + lane * 4]);
    float m = fmaxf(fmaxf(v.x, v.y), fmaxf(v.z, v.w));
    #pragma unroll
    for (int o = 16; o; o >>= 1) m = fmaxf(m, __shfl_xor_sync(0xffffffffu, m, o));
    float s = expf(v.x - m) + expf(v.y - m) + expf(v.z - m) + expf(v.w - m);
    #pragma unroll
    for (int o = 16; o; o >>= 1) s += __shfl_xor_sync(0xffffffffu, s, o);
    float l = m + logf(s);
    float4 o4 = make_float4(v.x - l, v.y - l, v.z - l, v.w - l);
    *reinterpret_cast<float4*>(&out[(size_t)row * D + lane * 4]) = o4;
}

// ---------------- launch ----------------
extern "C" void kernel_launch(void* const* d_in, const int* in_sizes, int n_in,
                              void* d_out, int out_size)
{
    const float* x      = (const float*)d_in[0];
    const int*   ei     = (const int*)d_in[1];
    const float* Ws     = (const float*)d_in[2];
    const float* gammas = (const float*)d_in[3];
    const float* betas  = (const float*)d_in[4];
    float* out = (float*)d_out;

    int n = in_sizes[0] / D;          // 100000
    int E = in_sizes[1] / 2;          // 1600000
    const int* src = ei;
    const int* dst = ei + E;

    int gemm_blocks = (n + 31) / 32;
    int scat_blocks = (int)(((size_t)E * 32 + 255) / 256);
    int lsm_blocks  = (int)(((size_t)n * 32 + 255) / 256);

    for (int layer = 0; layer < 3; layer++) {
        const float* W = Ws + (size_t)layer * D * D;
        // GEMM (reads x for layer 0, else g_agg with fused BN+ReLU)
        gemm_kernel<<<gemm_blocks, 128>>>(layer == 0 ? x : nullptr, W,
                                          layer == 0 ? 0 : 1);
        // zero accumulator, then scatter-add messages
        zero_agg_kernel<<<2048, 256>>>();
        scatter_kernel<<<scat_blocks, 256>>>(src, dst, E);

        if (layer < 2) {
            zero_stats_kernel<<<1, 256>>>();
            stats_kernel<<<1184, 256>>>(n);
            ab_kernel<<<1, 128>>>(gammas + (size_t)layer * D,
                                  betas + (size_t)layer * D, n);
        }
    }
    lsm_kernel<<<lsm_blocks, 256>>>(out, n);
}

// round 4
// speedup vs baseline: 1.6071x; 1.6071x over previous
#include <cuda_runtime.h>
#include <math.h>

#define N_NODES 100000
#define D 128
#define BN_EPS 1e-5f
#define MAXE 1600000
#define SCAN_BLK 1024
#define NBLK_MAX 128

// ---------------- scratch (__device__ globals, allocation-free) ----------------
__device__ float g_h[(size_t)N_NODES * D];     // GEMM output
__device__ float g_agg[(size_t)N_NODES * D];   // aggregated features
__device__ float g_stats[2 * D];               // per-col sum, sumsq (zeroed by ab_kernel)
__device__ float g_ab[2 * D];                  // BN affine
__device__ int   g_deg[N_NODES + 1];
__device__ int   g_cnt[N_NODES];
__device__ int   g_lp[N_NODES + 2];            // per-block-local exclusive scan of deg
__device__ int   g_bsum[NBLK_MAX];
__device__ int   g_bpre[NBLK_MAX];
__device__ int   g_csr[MAXE];                  // src ids grouped by dst

// ---------------- small helpers ----------------
__device__ __forceinline__ unsigned long long pack2(float a, float b) {
    unsigned long long r;
    asm("mov.b64 %0, {%1,%2};" : "=l"(r) : "f"(a), "f"(b));
    return r;
}
__device__ __forceinline__ void unpack2(unsigned long long v, float& lo, float& hi) {
    asm("mov.b64 {%0,%1}, %2;" : "=f"(lo), "=f"(hi) : "l"(v));
}
__device__ __forceinline__ void fma2(unsigned long long& acc, unsigned long long a,
                                     unsigned long long b) {
    asm("fma.rn.f32x2 %0, %1, %2, %0;" : "+l"(acc) : "l"(a), "l"(b));
}

// ---------------- CSR build ----------------
__global__ void zero_kernel(int n) {
    for (int i = blockIdx.x * blockDim.x + threadIdx.x; i <= n;
         i += gridDim.x * blockDim.x) {
        g_deg[i] = 0;
        if (i < n) g_cnt[i] = 0;
        if (i < 2 * D) g_stats[i] = 0.f;
    }
}

__global__ void count_kernel(const int* __restrict__ dst, int E) {
    for (int e = blockIdx.x * blockDim.x + threadIdx.x; e < E;
         e += gridDim.x * blockDim.x)
        atomicAdd(&g_deg[dst[e]], 1);
}

__global__ __launch_bounds__(SCAN_BLK) void scan_part_kernel(int n) {
    int tid = threadIdx.x;
    int i = blockIdx.x * SCAN_BLK + tid;
    int lane = tid & 31, wid = tid >> 5;
    int v = (i < n) ? g_deg[i] : 0;
    int x = v;
    #pragma unroll
    for (int off = 1; off < 32; off <<= 1) {
        int t = __shfl_up_sync(0xffffffffu, x, off);
        if (lane >= off) x += t;
    }
    __shared__ int wsum[32];
    if (lane == 31) wsum[wid] = x;
    __syncthreads();
    if (wid == 0) {
        int w = wsum[lane];
        int wx = w;
        #pragma unroll
        for (int off = 1; off < 32; off <<= 1) {
            int t = __shfl_up_sync(0xffffffffu, wx, off);
            if (lane >= off) wx += t;
        }
        wsum[lane] = wx - w;  // exclusive
    }
    __syncthreads();
    int incl = x + wsum[wid];
    if (i <= n) g_lp[i] = incl - v;
    if (tid == SCAN_BLK - 1) g_bsum[blockIdx.x] = incl;
}

__global__ void scan_sums_kernel(int nblk) {
    __shared__ int sh[NBLK_MAX];
    int t = threadIdx.x;
    int v = (t < nblk) ? g_bsum[t] : 0;
    sh[t] = v;
    __syncthreads();
    for (int off = 1; off < NBLK_MAX; off <<= 1) {
        int add = (t >= off) ? sh[t - off] : 0;
        __syncthreads();
        sh[t] += add;
        __syncthreads();
    }
    if (t < nblk) g_bpre[t] = sh[t] - v;  // exclusive
}

__global__ void fill_kernel(const int* __restrict__ src,
                            const int* __restrict__ dst, int E) {
    for (int e = blockIdx.x * blockDim.x + threadIdx.x; e < E;
         e += gridDim.x * blockDim.x) {
        int d = dst[e];
        int pos = g_lp[d] + g_bpre[d >> 10] + atomicAdd(&g_cnt[d], 1);
        g_csr[pos] = src[e];
    }
}

// ---------------- GEMM: H = f(X) @ W  (FFMA2, 64x128 tile, 8x4 per thread) ----
__global__ __launch_bounds__(256) void gemm_kernel(
    const float* __restrict__ Xin,   // null => g_agg
    const float* __restrict__ W, int use_bn, int n)
{
    __shared__ __align__(16) float xs[D][66];  // [k][row], stride 66 -> aligned pairs
    const float* X = Xin ? Xin : g_agg;
    int tid = threadIdx.x;
    int cg = tid & 31;          // col group: cols 4cg..4cg+3
    int rg = tid >> 5;          // row group: rows 8rg..8rg+7
    int row0 = blockIdx.x * 64;
    int col = tid & 127;
    int rsub = tid >> 7;

    float a = 1.f, b = 0.f;
    if (use_bn) { a = g_ab[col]; b = g_ab[D + col]; }

    #pragma unroll 8
    for (int it = 0; it < 32; it++) {
        int r = it * 2 + rsub;
        int grow = row0 + r;
        float v = 0.f;
        if (grow < n) {
            v = X[(size_t)grow * D + col];
            if (use_bn) v = fmaxf(fmaf(v, a, b), 0.f);
        }
        xs[col][r] = v;
    }
    __syncthreads();

    unsigned long long acc[4][4] = {};
    const float* Wp = W + cg * 4;

    #pragma unroll 2
    for (int k = 0; k < D; k++) {
        float4 w = __ldg(reinterpret_cast<const float4*>(Wp + (size_t)k * D));
        unsigned long long wx = pack2(w.x, w.x);
        unsigned long long wy = pack2(w.y, w.y);
        unsigned long long wz = pack2(w.z, w.z);
        unsigned long long ww = pack2(w.w, w.w);
        const float* xk = &xs[k][rg * 8];
        #pragma unroll
        for (int rp = 0; rp < 4; rp++) {
            unsigned long long x2 =
                *reinterpret_cast<const unsigned long long*>(xk + rp * 2);
            fma2(acc[rp][0], x2, wx);
            fma2(acc[rp][1], x2, wy);
            fma2(acc[rp][2], x2, wz);
            fma2(acc[rp][3], x2, ww);
        }
    }

    #pragma unroll
    for (int rp = 0; rp < 4; rp++) {
        float lo[4], hi[4];
        #pragma unroll
        for (int c = 0; c < 4; c++) unpack2(acc[rp][c], lo[c], hi[c]);
        int r = row0 + rg * 8 + rp * 2;
        if (r < n)
            *reinterpret_cast<float4*>(&g_h[(size_t)r * D + cg * 4]) =
                make_float4(lo[0], lo[1], lo[2], lo[3]);
        if (r + 1 < n)
            *reinterpret_cast<float4*>(&g_h[(size_t)(r + 1) * D + cg * 4]) =
                make_float4(hi[0], hi[1], hi[2], hi[3]);
    }
}

// ---------------- gather: agg[d] = sum_{e in CSR[d]} h[src[e]] ----------------
// warp per dst node; optional fused BN stats / fused log_softmax.
__global__ __launch_bounds__(256) void gather_kernel(int do_stats,
                                                     float* __restrict__ out,
                                                     int n)
{
    __shared__ float sh_s[8][D], sh_q[8][D];
    int tid = threadIdx.x;
    int w = tid >> 5, lane = tid & 31;
    int d = blockIdx.x * 8 + w;
    bool valid = d < n;

    float4 acc = make_float4(0.f, 0.f, 0.f, 0.f);
    if (valid) {
        int start = g_lp[d] + g_bpre[d >> 10];
        int end   = g_lp[d + 1] + g_bpre[(d + 1) >> 10];
        for (int base = start; base < end; base += 32) {
            int rem = end - base;
            int s_l = 0;
            if (lane < rem) s_l = g_csr[base + lane];
            int c = rem < 32 ? rem : 32;
            for (int i = 0; i < c; i++) {
                int s = __shfl_sync(0xffffffffu, s_l, i);
                float4 v = *reinterpret_cast<const float4*>(
                    &g_h[(size_t)s * D + lane * 4]);
                acc.x += v.x; acc.y += v.y; acc.z += v.z; acc.w += v.w;
            }
        }
    }

    if (out) {  // final layer: log_softmax straight to output
        if (!valid) return;
        float m = fmaxf(fmaxf(acc.x, acc.y), fmaxf(acc.z, acc.w));
        #pragma unroll
        for (int o = 16; o; o >>= 1) m = fmaxf(m, __shfl_xor_sync(0xffffffffu, m, o));
        float s = expf(acc.x - m) + expf(acc.y - m) + expf(acc.z - m) + expf(acc.w - m);
        #pragma unroll
        for (int o = 16; o; o >>= 1) s += __shfl_xor_sync(0xffffffffu, s, o);
        float l = m + logf(s);
        *reinterpret_cast<float4*>(&out[(size_t)d * D + lane * 4]) =
            make_float4(acc.x - l, acc.y - l, acc.z - l, acc.w - l);
        return;
    }

    if (valid)
        *reinterpret_cast<float4*>(&g_agg[(size_t)d * D + lane * 4]) = acc;

    if (do_stats) {
        int c0 = lane * 4;
        sh_s[w][c0 + 0] = acc.x; sh_s[w][c0 + 1] = acc.y;
        sh_s[w][c0 + 2] = acc.z; sh_s[w][c0 + 3] = acc.w;
        sh_q[w][c0 + 0] = acc.x * acc.x; sh_q[w][c0 + 1] = acc.y * acc.y;
        sh_q[w][c0 + 2] = acc.z * acc.z; sh_q[w][c0 + 3] = acc.w * acc.w;
        __syncthreads();
        if (tid < D) {
            float s = 0.f, q = 0.f;
            #pragma unroll
            for (int j = 0; j < 8; j++) { s += sh_s[j][tid]; q += sh_q[j][tid]; }
            atomicAdd(&g_stats[tid], s);
            atomicAdd(&g_stats[D + tid], q);
        }
    }
}

// ---------------- BN affine coefficients (and self-reset of stats) -----------
__global__ void ab_kernel(const float* __restrict__ gamma,
                          const float* __restrict__ beta, int n)
{
    int col = threadIdx.x;
    if (col >= D) return;
    float inv_n = 1.f / (float)n;
    float mu = g_stats[col] * inv_n;
    float var = fmaf(-mu, mu, g_stats[D + col] * inv_n);
    float inv = rsqrtf(var + BN_EPS);
    float a = gamma[col] * inv;
    g_ab[col] = a;
    g_ab[D + col] = fmaf(-mu, a, beta[col]);
    g_stats[col] = 0.f;         // ready for next layer / next replay
    g_stats[D + col] = 0.f;
}

// ---------------- launch ----------------
extern "C" void kernel_launch(void* const* d_in, const int* in_sizes, int n_in,
                              void* d_out, int out_size)
{
    const float* x      = (const float*)d_in[0];
    const int*   ei     = (const int*)d_in[1];
    const float* Ws     = (const float*)d_in[2];
    const float* gammas = (const float*)d_in[3];
    const float* betas  = (const float*)d_in[4];
    float* out = (float*)d_out;

    int n = in_sizes[0] / D;          // 100000
    int E = in_sizes[1] / 2;          // 1600000
    const int* src = ei;
    const int* dst = ei + E;

    int nblk = (n + SCAN_BLK) / SCAN_BLK;   // covers i in [0, n]
    int gemm_blocks = (n + 63) / 64;
    int gath_blocks = (n + 7) / 8;
    int eblocks = (E + 255) / 256;

    // CSR build (once per call)
    zero_kernel<<<128, 1024>>>(n);
    count_kernel<<<eblocks, 256>>>(dst, E);
    scan_part_kernel<<<nblk, SCAN_BLK>>>(n);
    scan_sums_kernel<<<1, NBLK_MAX>>>(nblk);
    fill_kernel<<<eblocks, 256>>>(src, dst, E);

    for (int layer = 0; layer < 3; layer++) {
        const float* W = Ws + (size_t)layer * D * D;
        gemm_kernel<<<gemm_blocks, 256>>>(layer == 0 ? x : nullptr, W,
                                          layer == 0 ? 0 : 1, n);
        if (layer < 2) {
            gather_kernel<<<gath_blocks, 256>>>(1, nullptr, n);
            ab_kernel<<<1, 128>>>(gammas + (size_t)layer * D,
                                  betas + (size_t)layer * D, n);
        } else {
            gather_kernel<<<gath_blocks, 256>>>(0, out, n);
        }
    }
}

// round 8
// speedup vs baseline: 1.6553x; 1.0300x over previous
#include <cuda_runtime.h>
#include <math.h>

#define N_NODES 100000
#define D 128
#define BN_EPS 1e-5f
#define MAXE 1600000
#define SCAN_BLK 1024
#define NBLK_MAX 128

// ---------------- scratch (__device__ globals, allocation-free) ----------------
__device__ float g_h[(size_t)N_NODES * D];     // GEMM output
__device__ float g_agg[(size_t)N_NODES * D];   // aggregated features
__device__ float g_stats0[2 * D];              // layer-0 per-col sum, sumsq
__device__ float g_stats1[2 * D];              // layer-1 per-col sum, sumsq
__device__ int   g_deg[N_NODES + 1];
__device__ int   g_cnt[N_NODES];
__device__ int   g_lp[N_NODES + 2];            // per-block-local exclusive scan of deg
__device__ int   g_bsum[NBLK_MAX];
__device__ int   g_bpre[NBLK_MAX];
__device__ int   g_csr[MAXE];                  // src ids grouped by dst

// ---------------- small helpers ----------------
__device__ __forceinline__ unsigned long long pack2(float a, float b) {
    unsigned long long r;
    asm("mov.b64 %0, {%1,%2};" : "=l"(r) : "f"(a), "f"(b));
    return r;
}
__device__ __forceinline__ void unpack2(unsigned long long v, float& lo, float& hi) {
    asm("mov.b64 {%0,%1}, %2;" : "=f"(lo), "=f"(hi) : "l"(v));
}
__device__ __forceinline__ void fma2(unsigned long long& acc, unsigned long long a,
                                     unsigned long long b) {
    asm("fma.rn.f32x2 %0, %1, %2, %0;" : "+l"(acc) : "l"(a), "l"(b));
}

// ---------------- CSR build ----------------
__global__ void zero_kernel(int n) {
    for (int i = blockIdx.x * blockDim.x + threadIdx.x; i <= n;
         i += gridDim.x * blockDim.x) {
        g_deg[i] = 0;
        if (i < n) g_cnt[i] = 0;
        if (i < 2 * D) { g_stats0[i] = 0.f; g_stats1[i] = 0.f; }
    }
}

__global__ void count_kernel(const int* __restrict__ dst, int E) {
    for (int e = blockIdx.x * blockDim.x + threadIdx.x; e < E;
         e += gridDim.x * blockDim.x)
        atomicAdd(&g_deg[dst[e]], 1);
}

__global__ __launch_bounds__(SCAN_BLK) void scan_part_kernel(int n) {
    int tid = threadIdx.x;
    int i = blockIdx.x * SCAN_BLK + tid;
    int lane = tid & 31, wid = tid >> 5;
    int v = (i < n) ? g_deg[i] : 0;
    int x = v;
    #pragma unroll
    for (int off = 1; off < 32; off <<= 1) {
        int t = __shfl_up_sync(0xffffffffu, x, off);
        if (lane >= off) x += t;
    }
    __shared__ int wsum[32];
    if (lane == 31) wsum[wid] = x;
    __syncthreads();
    if (wid == 0) {
        int w = wsum[lane];
        int wx = w;
        #pragma unroll
        for (int off = 1; off < 32; off <<= 1) {
            int t = __shfl_up_sync(0xffffffffu, wx, off);
            if (lane >= off) wx += t;
        }
        wsum[lane] = wx - w;  // exclusive
    }
    __syncthreads();
    int incl = x + wsum[wid];
    if (i <= n) g_lp[i] = incl - v;
    if (tid == SCAN_BLK - 1) g_bsum[blockIdx.x] = incl;
}

__global__ void scan_sums_kernel(int nblk) {
    __shared__ int sh[NBLK_MAX];
    int t = threadIdx.x;
    int v = (t < nblk) ? g_bsum[t] : 0;
    sh[t] = v;
    __syncthreads();
    for (int off = 1; off < NBLK_MAX; off <<= 1) {
        int add = (t >= off) ? sh[t - off] : 0;
        __syncthreads();
        sh[t] += add;
        __syncthreads();
    }
    if (t < nblk) g_bpre[t] = sh[t] - v;  // exclusive
}

__global__ void fill_kernel(const int* __restrict__ src,
                            const int* __restrict__ dst, int E) {
    for (int e = blockIdx.x * blockDim.x + threadIdx.x; e < E;
         e += gridDim.x * blockDim.x) {
        int d = dst[e];
        int pos = g_lp[d] + g_bpre[d >> 10] + atomicAdd(&g_cnt[d], 1);
        g_csr[pos] = src[e];
    }
}

// ---------------- GEMM: H = f(X) @ W  (FFMA2, 64x128 tile, 8x4 per thread) ----
// BN affine (a,b) computed inline from stats when stats != null.
__global__ __launch_bounds__(256) void gemm_kernel(
    const float* __restrict__ Xin,   // null => g_agg
    const float* __restrict__ W,
    const float* __restrict__ stats, // null => no BN
    const float* __restrict__ gamma,
    const float* __restrict__ beta,
    int n)
{
    __shared__ __align__(16) float xs[D][66];  // [k][row]
    const float* X = Xin ? Xin : g_agg;
    int tid = threadIdx.x;
    int cg = tid & 31;          // col group: cols 4cg..4cg+3
    int rg = tid >> 5;          // row group: rows 8rg..8rg+7
    int row0 = blockIdx.x * 64;
    int col = tid & 127;
    int rsub = tid >> 7;

    float a = 1.f, b = 0.f;
    if (stats) {
        float inv_n = 1.f / (float)n;
        float mu = stats[col] * inv_n;
        float var = fmaf(-mu, mu, stats[D + col] * inv_n);
        a = gamma[col] * rsqrtf(var + BN_EPS);
        b = fmaf(-mu, a, beta[col]);
    }

    #pragma unroll 8
    for (int it = 0; it < 32; it++) {
        int r = it * 2 + rsub;
        int grow = row0 + r;
        float v = 0.f;
        if (grow < n) {
            v = X[(size_t)grow * D + col];
            if (stats) v = fmaxf(fmaf(v, a, b), 0.f);
        }
        xs[col][r] = v;
    }
    __syncthreads();

    unsigned long long acc[4][4] = {};
    const float* Wp = W + cg * 4;

    #pragma unroll 2
    for (int k = 0; k < D; k++) {
        float4 w = __ldg(reinterpret_cast<const float4*>(Wp + (size_t)k * D));
        unsigned long long wx = pack2(w.x, w.x);
        unsigned long long wy = pack2(w.y, w.y);
        unsigned long long wz = pack2(w.z, w.z);
        unsigned long long ww = pack2(w.w, w.w);
        const float* xk = &xs[k][rg * 8];
        #pragma unroll
        for (int rp = 0; rp < 4; rp++) {
            unsigned long long x2 =
                *reinterpret_cast<const unsigned long long*>(xk + rp * 2);
            fma2(acc[rp][0], x2, wx);
            fma2(acc[rp][1], x2, wy);
            fma2(acc[rp][2], x2, wz);
            fma2(acc[rp][3], x2, ww);
        }
    }

    #pragma unroll
    for (int rp = 0; rp < 4; rp++) {
        float lo[4], hi[4];
        #pragma unroll
        for (int c = 0; c < 4; c++) unpack2(acc[rp][c], lo[c], hi[c]);
        int r = row0 + rg * 8 + rp * 2;
        if (r < n)
            *reinterpret_cast<float4*>(&g_h[(size_t)r * D + cg * 4]) =
                make_float4(lo[0], lo[1], lo[2], lo[3]);
        if (r + 1 < n)
            *reinterpret_cast<float4*>(&g_h[(size_t)(r + 1) * D + cg * 4]) =
                make_float4(hi[0], hi[1], hi[2], hi[3]);
    }
}

// ---------------- gather: agg[d] = sum_{e in CSR[d]} h[src[e]] ----------------
// warp per dst node; src indices via warp-uniform broadcast LDG; 8-way unrolled
// for MLP. Optional fused BN stats / fused log_softmax.
__global__ __launch_bounds__(256) void gather_kernel(float* __restrict__ stats_out,
                                                     float* __restrict__ out,
                                                     int n)
{
    __shared__ float sh_s[8][D], sh_q[8][D];
    int tid = threadIdx.x;
    int w = tid >> 5, lane = tid & 31;
    int d = blockIdx.x * 8 + w;
    bool valid = d < n;
    int cb = lane * 4;  // this lane's column base

    float4 acc = make_float4(0.f, 0.f, 0.f, 0.f);
    if (valid) {
        int i   = g_lp[d] + g_bpre[d >> 10];
        int end = g_lp[d + 1] + g_bpre[(d + 1) >> 10];
        for (; i + 8 <= end; i += 8) {
            int s0 = __ldg(&g_csr[i + 0]);
            int s1 = __ldg(&g_csr[i + 1]);
            int s2 = __ldg(&g_csr[i + 2]);
            int s3 = __ldg(&g_csr[i + 3]);
            int s4 = __ldg(&g_csr[i + 4]);
            int s5 = __ldg(&g_csr[i + 5]);
            int s6 = __ldg(&g_csr[i + 6]);
            int s7 = __ldg(&g_csr[i + 7]);
            float4 v0 = __ldg(reinterpret_cast<const float4*>(&g_h[(size_t)s0 * D + cb]));
            float4 v1 = __ldg(reinterpret_cast<const float4*>(&g_h[(size_t)s1 * D + cb]));
            float4 v2 = __ldg(reinterpret_cast<const float4*>(&g_h[(size_t)s2 * D + cb]));
            float4 v3 = __ldg(reinterpret_cast<const float4*>(&g_h[(size_t)s3 * D + cb]));
            float4 v4 = __ldg(reinterpret_cast<const float4*>(&g_h[(size_t)s4 * D + cb]));
            float4 v5 = __ldg(reinterpret_cast<const float4*>(&g_h[(size_t)s5 * D + cb]));
            float4 v6 = __ldg(reinterpret_cast<const float4*>(&g_h[(size_t)s6 * D + cb]));
            float4 v7 = __ldg(reinterpret_cast<const float4*>(&g_h[(size_t)s7 * D + cb]));
            acc.x += (v0.x + v1.x) + (v2.x + v3.x) + ((v4.x + v5.x) + (v6.x + v7.x));
            acc.y += (v0.y + v1.y) + (v2.y + v3.y) + ((v4.y + v5.y) + (v6.y + v7.y));
            acc.z += (v0.z + v1.z) + (v2.z + v3.z) + ((v4.z + v5.z) + (v6.z + v7.z));
            acc.w += (v0.w + v1.w) + (v2.w + v3.w) + ((v4.w + v5.w) + (v6.w + v7.w));
        }
        for (; i + 4 <= end; i += 4) {
            int s0 = __ldg(&g_csr[i + 0]);
            int s1 = __ldg(&g_csr[i + 1]);
            int s2 = __ldg(&g_csr[i + 2]);
            int s3 = __ldg(&g_csr[i + 3]);
            float4 v0 = __ldg(reinterpret_cast<const float4*>(&g_h[(size_t)s0 * D + cb]));
            float4 v1 = __ldg(reinterpret_cast<const float4*>(&g_h[(size_t)s1 * D + cb]));
            float4 v2 = __ldg(reinterpret_cast<const float4*>(&g_h[(size_t)s2 * D + cb]));
            float4 v3 = __ldg(reinterpret_cast<const float4*>(&g_h[(size_t)s3 * D + cb]));
            acc.x += v0.x + v1.x + v2.x + v3.x;
            acc.y += v0.y + v1.y + v2.y + v3.y;
            acc.z += v0.z + v1.z + v2.z + v3.z;
            acc.w += v0.w + v1.w + v2.w + v3.w;
        }
        for (; i < end; i++) {
            int s = __ldg(&g_csr[i]);
            float4 v = __ldg(reinterpret_cast<const float4*>(&g_h[(size_t)s * D + cb]));
            acc.x += v.x; acc.y += v.y; acc.z += v.z; acc.w += v.w;
        }
    }

    if (out) {  // final layer: log_softmax straight to output
        if (!valid) return;
        float m = fmaxf(fmaxf(acc.x, acc.y), fmaxf(acc.z, acc.w));
        #pragma unroll
        for (int o = 16; o; o >>= 1) m = fmaxf(m, __shfl_xor_sync(0xffffffffu, m, o));
        float s = expf(acc.x - m) + expf(acc.y - m) + expf(acc.z - m) + expf(acc.w - m);
        #pragma unroll
        for (int o = 16; o; o >>= 1) s += __shfl_xor_sync(0xffffffffu, s, o);
        float l = m + logf(s);
        *reinterpret_cast<float4*>(&out[(size_t)d * D + cb]) =
            make_float4(acc.x - l, acc.y - l, acc.z - l, acc.w - l);
        return;
    }

    if (valid)
        *reinterpret_cast<float4*>(&g_agg[(size_t)d * D + cb]) = acc;

    // fused BN column stats (invalid warps contribute exact zeros)
    sh_s[w][cb + 0] = acc.x; sh_s[w][cb + 1] = acc.y;
    sh_s[w][cb + 2] = acc.z; sh_s[w][cb + 3] = acc.w;
    sh_q[w][cb + 0] = acc.x * acc.x; sh_q[w][cb + 1] = acc.y * acc.y;
    sh_q[w][cb + 2] = acc.z * acc.z; sh_q[w][cb + 3] = acc.w * acc.w;
    __syncthreads();
    if (tid < D) {
        float s = 0.f, q = 0.f;
        #pragma unroll
        for (int j = 0; j < 8; j++) { s += sh_s[j][tid]; q += sh_q[j][tid]; }
        atomicAdd(&stats_out[tid], s);
        atomicAdd(&stats_out[D + tid], q);
    }
}

// ---------------- launch ----------------
extern "C" void kernel_launch(void* const* d_in, const int* in_sizes, int n_in,
                              void* d_out, int out_size)
{
    const float* x      = (const float*)d_in[0];
    const int*   ei     = (const int*)d_in[1];
    const float* Ws     = (const float*)d_in[2];
    const float* gammas = (const float*)d_in[3];
    const float* betas  = (const float*)d_in[4];
    float* out = (float*)d_out;

    int n = in_sizes[0] / D;          // 100000
    int E = in_sizes[1] / 2;          // 1600000
    const int* src = ei;
    const int* dst = ei + E;

    float* d_stats0; cudaGetSymbolAddress((void**)&d_stats0, g_stats0);
    float* d_stats1; cudaGetSymbolAddress((void**)&d_stats1, g_stats1);
    float* statsArr[2] = {d_stats0, d_stats1};

    int nblk = (n + SCAN_BLK) / SCAN_BLK;   // covers i in [0, n]
    int gemm_blocks = (n + 63) / 64;
    int gath_blocks = (n + 7) / 8;
    int eblocks = (E + 255) / 256;

    // CSR build (once per call)
    zero_kernel<<<128, 1024>>>(n);
    count_kernel<<<eblocks, 256>>>(dst, E);
    scan_part_kernel<<<nblk, SCAN_BLK>>>(n);
    scan_sums_kernel<<<1, NBLK_MAX>>>(nblk);
    fill_kernel<<<eblocks, 256>>>(src, dst, E);

    for (int layer = 0; layer < 3; layer++) {
        const float* W = Ws + (size_t)layer * D * D;
        gemm_kernel<<<gemm_blocks, 256>>>(
            layer == 0 ? x : nullptr, W,
            layer == 0 ? nullptr : statsArr[layer - 1],
            layer == 0 ? nullptr : gammas + (size_t)(layer - 1) * D,
            layer == 0 ? nullptr : betas + (size_t)(layer - 1) * D, n);
        if (layer < 2)
            gather_kernel<<<gath_blocks, 256>>>(statsArr[layer], nullptr, n);
        else
            gather_kernel<<<gath_blocks, 256>>>(nullptr, out, n);
    }
}